// round 10
// baseline (speedup 1.0000x reference)
#include <cuda_runtime.h>
#include <cstdint>

// Sobel edge magnitude + channel mean.
// x: [B=16, C=64, H=256, W=256] f32 -> out: [B,1,H,W] f32
//
// R10: warp-private cp.async smem pipeline (depth 2). Each warp stages its
// next channel strips global->smem with LDGSTS, so in-flight memory no longer
// consumes registers (R7/R9 showed RF-resident prefetch caps out at 128 regs
// and kills occupancy). 3 CTAs/SM, ~60 regs, smem 67KB/CTA (dynamic).

#define BB 16
#define CC 64
#define HH 256
#define WW 256
#define RR 4            // output rows per strip
#define NROWS (RR + 2)
#define NWARPS 8
#define TW 128          // columns per warp tile
#define HSTRIPS (HH / RR)
#define KITERS (CC / NWARPS)
#define ROWF 132        // floats per staged row: 128 data + hl + hr + pad
#define STRIPF (NROWS * ROWF)          // floats per strip buffer
#define PIPEF (NWARPS * 2 * STRIPF)    // all pipeline buffers
#define ACCF (NWARPS * RR * TW)        // per-warp partial sums
#define SMEM_BYTES ((PIPEF + ACCF) * 4)

typedef unsigned long long u64;

__device__ __forceinline__ float sqrt_approx(float v) {
    float y; asm("sqrt.approx.f32 %0, %1;" : "=f"(y) : "f"(v)); return y;
}
__device__ __forceinline__ u64 pk(float lo, float hi) {
    u64 r; asm("mov.b64 %0, {%1, %2};" : "=l"(r) : "f"(lo), "f"(hi)); return r;
}
__device__ __forceinline__ void upk(float& lo, float& hi, u64 v) {
    asm("mov.b64 {%0, %1}, %2;" : "=f"(lo), "=f"(hi) : "l"(v));
}
__device__ __forceinline__ u64 add2(u64 a, u64 b) {
    u64 r; asm("add.rn.f32x2 %0, %1, %2;" : "=l"(r) : "l"(a), "l"(b)); return r;
}
__device__ __forceinline__ u64 fma2(u64 a, u64 b, u64 c) {
    u64 r; asm("fma.rn.f32x2 %0, %1, %2, %3;" : "=l"(r) : "l"(a), "l"(b), "l"(c)); return r;
}
__device__ __forceinline__ void cp16(uint32_t daddr, const float* src) {
    asm volatile("cp.async.ca.shared.global [%0], [%1], 16;" :: "r"(daddr), "l"(src));
}
__device__ __forceinline__ void cp4(uint32_t daddr, const float* src) {
    asm volatile("cp.async.ca.shared.global [%0], [%1], 4;" :: "r"(daddr), "l"(src));
}
__device__ __forceinline__ void cp_commit() {
    asm volatile("cp.async.commit_group;");
}
__device__ __forceinline__ void cp_wait1() {
    asm volatile("cp.async.wait_group 1;");
}

extern __shared__ float smem[];

// Stage one channel strip (6 rows + halos) into this warp's smem buffer.
__device__ __forceinline__ void stage_strip(
    uint32_t buf_addr,                 // shared-space byte address of buffer
    const float* __restrict__ plane,
    int gh0, int gw4, int lane,
    bool top_oob, bool bot_oob, bool has_left, bool has_right)
{
#pragma unroll
    for (int i = 0; i < NROWS; i++) {
        const bool oob = (i == 0 && top_oob) || (i == NROWS - 1 && bot_oob);
        if (!oob) {
            const int gh = gh0 - 1 + i;
            const float* __restrict__ row = plane + gh * WW;
            const uint32_t rbase = buf_addr + (uint32_t)(i * ROWF * 4);
            cp16(rbase + (uint32_t)(lane * 16), row + gw4);
            if (lane == 0 && has_left)
                cp4(rbase + 128u * 4u, row + gw4 - 1);
            if (lane == 31 && has_right)
                cp4(rbase + 129u * 4u, row + gw4 + 4);
        }
    }
}

// Consume one staged strip; accumulate Sobel magnitudes into acc[].
__device__ __forceinline__ void compute_strip(
    const float* __restrict__ buf, float4* acc,
    int lane, int idx_l, int idx_r, bool zl, bool zr,
    bool top_oob, bool bot_oob,
    u64 TWO2, u64 NEG1, u64 EPS2)
{
    u64 p0l = 0, p0h = 0, p1l = 0, p1h = 0;
    u64 q0l = 0, q0h = 0, q1l = 0, q1h = 0;
#pragma unroll
    for (int i = 0; i < NROWS; i++) {
        const bool oob = (i == 0 && top_oob) || (i == NROWS - 1 && bot_oob);
        u64 pl, ph, ql, qh;
        if (oob) {
            pl = ph = ql = qh = 0;
        } else {
            const float* __restrict__ srow = buf + i * ROWF;
            const float4 v = *reinterpret_cast<const float4*>(srow + lane * 4);
            float l = srow[idx_l];
            float r = srow[idx_r];
            if (zl) l = 0.f;
            if (zr) r = 0.f;
            const u64 cl = pk(v.x, v.y);
            const u64 ch = pk(v.z, v.w);
            const u64 ll = pk(l,   v.x);
            const u64 lh = pk(v.y, v.z);
            const u64 rh = pk(v.w, r);
            pl = fma2(NEG1, ll, lh);               // right - left
            ph = fma2(NEG1, lh, rh);
            ql = add2(fma2(cl, TWO2, ll), lh);     // l + 2c + r
            qh = add2(fma2(ch, TWO2, lh), rh);
        }
        if (i >= 2) {
            const int rr = i - 2;
            const u64 gxl = add2(fma2(p1l, TWO2, p0l), pl);
            const u64 gxh = add2(fma2(p1h, TWO2, p0h), ph);
            const u64 gyl = fma2(NEG1, q0l, ql);
            const u64 gyh = fma2(NEG1, q0h, qh);
            const u64 m_l = fma2(gxl, gxl, fma2(gyl, gyl, EPS2));
            const u64 m_h = fma2(gxh, gxh, fma2(gyh, gyh, EPS2));
            float m0, m1, m2, m3;
            upk(m0, m1, m_l);
            upk(m2, m3, m_h);
            acc[rr].x += sqrt_approx(m0);
            acc[rr].y += sqrt_approx(m1);
            acc[rr].z += sqrt_approx(m2);
            acc[rr].w += sqrt_approx(m3);
        }
        p0l = p1l; p0h = p1h; p1l = pl; p1h = ph;
        q0l = q1l; q0h = q1h; q1l = ql; q1h = qh;
    }
}

__global__ __launch_bounds__(256, 3)
void sobel_mean_kernel(const float* __restrict__ x, float* __restrict__ out) {
    const int wq   = blockIdx.x;
    const int hs   = blockIdx.y;
    const int b    = blockIdx.z;
    const int tid  = threadIdx.x;
    const int wid  = tid >> 5;
    const int lane = tid & 31;

    const int gw4 = wq * TW + lane * 4;
    const int gh0 = hs * RR;

    const bool top_oob = (hs == 0);
    const bool bot_oob = (hs == HSTRIPS - 1);
    const bool has_left  = (gw4 != 0);
    const bool has_right = (gw4 + 4 != WW);

    // neighbor indices within a staged row (lane-constant)
    const int idx_l = (lane == 0)  ? 128 : (4 * lane - 1);
    const int idx_r = (lane == 31) ? 129 : (4 * lane + 4);
    const bool zl = (lane == 0)  && !has_left;    // zero-pad at image edge
    const bool zr = (lane == 31) && !has_right;

    float* s_pipe = smem;
    float* s_acc  = smem + PIPEF;

    float* buf0 = s_pipe + (wid * 2 + 0) * STRIPF;
    float* buf1 = s_pipe + (wid * 2 + 1) * STRIPF;
    const uint32_t buf0a = (uint32_t)__cvta_generic_to_shared(buf0);
    const uint32_t buf1a = (uint32_t)__cvta_generic_to_shared(buf1);

    const u64 TWO2 = pk(2.0f, 2.0f);
    const u64 NEG1 = pk(-1.0f, -1.0f);
    const u64 EPS2 = pk(1e-12f, 1e-12f);

    float4 acc[RR];
#pragma unroll
    for (int r = 0; r < RR; r++) acc[r] = make_float4(0.f, 0.f, 0.f, 0.f);

    const float* __restrict__ plane0 =
        x + ((size_t)(b * CC + wid)) * (HH * WW);
    const size_t cstride = (size_t)NWARPS * (HH * WW);

    // Prologue: stage strips 0 and 1 (two outstanding groups).
    stage_strip(buf0a, plane0, gh0, gw4, lane,
                top_oob, bot_oob, has_left, has_right);
    cp_commit();
    stage_strip(buf1a, plane0 + cstride, gh0, gw4, lane,
                top_oob, bot_oob, has_left, has_right);
    cp_commit();

#pragma unroll 1
    for (int k = 0; k < KITERS; k += 2) {
        // strip k (buf0)
        cp_wait1();              // group for strip k complete
        __syncwarp();            // cross-lane visibility of staged data
        compute_strip(buf0, acc, lane, idx_l, idx_r, zl, zr,
                      top_oob, bot_oob, TWO2, NEG1, EPS2);
        __syncwarp();            // all lanes done reading before restage
        if (k + 2 < KITERS)
            stage_strip(buf0a, plane0 + (size_t)(k + 2) * cstride,
                        gh0, gw4, lane, top_oob, bot_oob, has_left, has_right);
        cp_commit();

        // strip k+1 (buf1)
        cp_wait1();
        __syncwarp();
        compute_strip(buf1, acc, lane, idx_l, idx_r, zl, zr,
                      top_oob, bot_oob, TWO2, NEG1, EPS2);
        __syncwarp();
        if (k + 3 < KITERS)
            stage_strip(buf1a, plane0 + (size_t)(k + 3) * cstride,
                        gh0, gw4, lane, top_oob, bot_oob, has_left, has_right);
        cp_commit();
    }

    // Per-warp partials -> block reduction across the 8 warps.
#pragma unroll
    for (int r = 0; r < RR; r++)
        *reinterpret_cast<float4*>(&s_acc[(wid * RR + r) * TW + lane * 4]) = acc[r];
    __syncthreads();

    const float inv = 1.0f / (float)CC;
#pragma unroll
    for (int j = 0; j < (RR * TW) / 256; j++) {
        const int px = tid + 256 * j;          // 0..511
        float s = 0.f;
#pragma unroll
        for (int w = 0; w < NWARPS; w++) s += s_acc[w * (RR * TW) + px];
        const int r   = px / TW;
        const int col = px % TW;
        out[((size_t)b * HH + (gh0 + r)) * WW + wq * TW + col] = s * inv;
    }
}

extern "C" void kernel_launch(void* const* d_in, const int* in_sizes, int n_in,
                              void* d_out, int out_size) {
    const float* x = (const float*)d_in[0];
    float* out = (float*)d_out;
    static int attr_set = 0;
    if (!attr_set) {
        cudaFuncSetAttribute(sobel_mean_kernel,
                             cudaFuncAttributeMaxDynamicSharedMemorySize,
                             SMEM_BYTES);
        attr_set = 1;
    }
    dim3 grid(WW / TW, HSTRIPS, BB);   // (2, 64, 16) = 2048 blocks
    sobel_mean_kernel<<<grid, 256, SMEM_BYTES>>>(x, out);
}

// round 11
// speedup vs baseline: 1.6281x; 1.6281x over previous
#include <cuda_runtime.h>

// Sobel edge magnitude + channel mean.
// x: [B=16, C=64, H=256, W=256] f32 -> out: [B,1,H,W] f32
//
// Separable: p_i = x[i][w+1]-x[i][w-1], q_i = x[i][w-1]+2x[i][w]+x[i][w+1]
//   gx(r) = p_r + 2 p_{r+1} + p_{r+2},   gy(r) = q_{r+2} - q_r
//
// R11 changes vs R8 (best: 57.8us):
//  - Interior column halos come from 2 SHFLs/row instead of 12 all-lane
//    scalar LDGs/strip (those cost 48 L1 wavefronts/strip). Only lanes 0/31
//    load the true tile-edge halo, merged into ONE predicated LDG per row.
//  - OOB rows are zeroed vectors; p=q=0 then falls out naturally, so the
//    phase-2 OOB branch is gone.
//  - prefetch.global.L2 of the next channel's strip (6 instr, 0 regs) turns
//    next-iteration consumes into L2 hits.

#define BB 16
#define CC 64
#define HH 256
#define WW 256
#define RR 4          // output rows per tile
#define NROWS (RR + 2)
#define NWARPS 8      // warps per block (channel stride)
#define TW 128        // columns per warp tile (32 lanes * 4)
#define HSTRIPS (HH / RR)
#define KITERS (CC / NWARPS)

typedef unsigned long long u64;

__device__ __forceinline__ float sqrt_approx(float v) {
    float y; asm("sqrt.approx.f32 %0, %1;" : "=f"(y) : "f"(v)); return y;
}
__device__ __forceinline__ u64 pk(float lo, float hi) {
    u64 r; asm("mov.b64 %0, {%1, %2};" : "=l"(r) : "f"(lo), "f"(hi)); return r;
}
__device__ __forceinline__ void upk(float& lo, float& hi, u64 v) {
    asm("mov.b64 {%0, %1}, %2;" : "=f"(lo), "=f"(hi) : "l"(v));
}
__device__ __forceinline__ u64 add2(u64 a, u64 b) {
    u64 r; asm("add.rn.f32x2 %0, %1, %2;" : "=l"(r) : "l"(a), "l"(b)); return r;
}
__device__ __forceinline__ u64 fma2(u64 a, u64 b, u64 c) {
    u64 r; asm("fma.rn.f32x2 %0, %1, %2, %3;" : "=l"(r) : "l"(a), "l"(b), "l"(c)); return r;
}
__device__ __forceinline__ void prefetch_l2(const float* p) {
    asm volatile("prefetch.global.L2 [%0];" :: "l"(p));
}

__global__ __launch_bounds__(256, 3)
void sobel_mean_kernel(const float* __restrict__ x, float* __restrict__ out) {
    const int wq   = blockIdx.x;   // column tile: 0..1
    const int hs   = blockIdx.y;   // row strip:   0..63
    const int b    = blockIdx.z;
    const int tid  = threadIdx.x;
    const int wid  = tid >> 5;
    const int lane = tid & 31;

    const int gw4 = wq * TW + lane * 4;
    const int gh0 = hs * RR;

    const bool top_oob = (hs == 0);
    const bool bot_oob = (hs == HSTRIPS - 1);
    const bool has_left  = (gw4 != 0);          // false only lane0 @ wq==0
    const bool has_right = (gw4 + 4 != WW);     // false only lane31 @ wq==1

    // One merged edge-halo load per row: lane0 loads col gw4-1, lane31 loads
    // col gw4+4; other lanes (and image-edge lanes) keep 0.
    const bool edge_ld = (lane == 0 && has_left) || (lane == 31 && has_right);
    const int  ha      = (lane == 0) ? (gw4 - 1) : (gw4 + 4);

    __shared__ float s_acc[NWARPS][RR * TW];   // 16 KB

    const u64 TWO2 = pk(2.0f, 2.0f);
    const u64 NEG1 = pk(-1.0f, -1.0f);
    const u64 EPS2 = pk(1e-12f, 1e-12f);
    const unsigned FULL = 0xFFFFFFFFu;

    float4 acc[RR];
#pragma unroll
    for (int r = 0; r < RR; r++) acc[r] = make_float4(0.f, 0.f, 0.f, 0.f);

    const float* __restrict__ plane0 =
        x + ((size_t)(b * CC + wid)) * (HH * WW);
    const size_t cstride = (size_t)NWARPS * (HH * WW);

#pragma unroll 1
    for (int k = 0; k < KITERS; k++) {
        const float* __restrict__ plane = plane0 + (size_t)k * cstride;

        // ---- Phase 1: batch all loads for the 6-row strip ----
        float4 vv[NROWS];
        float  hl[NROWS];
#pragma unroll
        for (int i = 0; i < NROWS; i++) {
            const int gh = gh0 - 1 + i;
            const bool oob = (i == 0 && top_oob) || (i == NROWS - 1 && bot_oob);
            const float* __restrict__ row = plane + gh * WW;
            vv[i] = make_float4(0.f, 0.f, 0.f, 0.f);
            hl[i] = 0.f;
            if (!oob) {
                vv[i] = *reinterpret_cast<const float4*>(row + gw4);
                if (edge_ld) hl[i] = row[ha];
            }
        }

        // Prefetch next channel's strip into L2 (no regs held).
        if (k + 1 < KITERS) {
            const float* __restrict__ np = plane + cstride;
#pragma unroll
            for (int i = 0; i < NROWS; i++) {
                const int gh = gh0 - 1 + i;
                const bool oob = (i == 0 && top_oob) || (i == NROWS - 1 && bot_oob);
                if (!oob) prefetch_l2(np + gh * WW + gw4);
            }
        }

        // ---- Phase 2: rolling p/q window; neighbors via SHFL ----
        u64 p0l = 0, p0h = 0, p1l = 0, p1h = 0;
        u64 q0l = 0, q0h = 0, q1l = 0, q1h = 0;
#pragma unroll
        for (int i = 0; i < NROWS; i++) {
            const float4 v = vv[i];
            float lft = __shfl_up_sync(FULL, v.w, 1);
            float rgt = __shfl_down_sync(FULL, v.x, 1);
            if (lane == 0)  lft = hl[i];
            if (lane == 31) rgt = hl[i];

            const u64 cl = pk(v.x, v.y);
            const u64 ch = pk(v.z, v.w);
            const u64 ll = pk(lft, v.x);
            const u64 lh = pk(v.y, v.z);
            const u64 rh = pk(v.w, rgt);

            const u64 pl = fma2(NEG1, ll, lh);            // r - l
            const u64 ph = fma2(NEG1, lh, rh);
            const u64 ql = add2(fma2(cl, TWO2, ll), lh);  // l + 2c + r
            const u64 qh = add2(fma2(ch, TWO2, lh), rh);

            if (i >= 2) {
                const int r = i - 2;
                const u64 gxl = add2(fma2(p1l, TWO2, p0l), pl);
                const u64 gxh = add2(fma2(p1h, TWO2, p0h), ph);
                const u64 gyl = fma2(NEG1, q0l, ql);
                const u64 gyh = fma2(NEG1, q0h, qh);
                const u64 m_l = fma2(gxl, gxl, fma2(gyl, gyl, EPS2));
                const u64 m_h = fma2(gxh, gxh, fma2(gyh, gyh, EPS2));
                float m0, m1, m2, m3;
                upk(m0, m1, m_l);
                upk(m2, m3, m_h);
                acc[r].x += sqrt_approx(m0);
                acc[r].y += sqrt_approx(m1);
                acc[r].z += sqrt_approx(m2);
                acc[r].w += sqrt_approx(m3);
            }
            p0l = p1l; p0h = p1h; p1l = pl; p1h = ph;
            q0l = q1l; q0h = q1h; q1l = ql; q1h = qh;
        }
    }

    // Stage per-warp partials, then block-reduce across the 8 warps.
#pragma unroll
    for (int r = 0; r < RR; r++)
        *reinterpret_cast<float4*>(&s_acc[wid][r * TW + lane * 4]) = acc[r];
    __syncthreads();

    const float inv = 1.0f / (float)CC;
#pragma unroll
    for (int j = 0; j < (RR * TW) / 256; j++) {
        const int px = tid + 256 * j;          // 0..511
        float s = 0.f;
#pragma unroll
        for (int w = 0; w < NWARPS; w++) s += s_acc[w][px];
        const int r   = px / TW;
        const int col = px % TW;
        out[((size_t)b * HH + (gh0 + r)) * WW + wq * TW + col] = s * inv;
    }
}

extern "C" void kernel_launch(void* const* d_in, const int* in_sizes, int n_in,
                              void* d_out, int out_size) {
    const float* x = (const float*)d_in[0];
    float* out = (float*)d_out;
    dim3 grid(WW / TW, HSTRIPS, BB);   // (2, 64, 16) = 2048 blocks
    sobel_mean_kernel<<<grid, 256>>>(x, out);
}